// round 11
// baseline (speedup 1.0000x reference)
#include <cuda_runtime.h>
#include <cuda_bf16.h>
#include <cstdint>

// Problem constants
#define BB 32
#define CC 64
#define TT 4096
#define NVEC ((BB * CC * TT) / 4)   // 2,097,152 float4 vectors
#define TVEC (TT / 4)               // 1024

#define GRID 1024
#define BLOCK 256
#define NWARPS (BLOCK / 32)
#define VPB (NVEC / GRID)           // 2048 vectors per block (contiguous)
#define CHUNKV BLOCK                // 256 vectors per stage (1 per thread)
#define NSTG (VPB / CHUNKV)         // 8 stages
#define DEPTH 4                     // pipeline depth
#define STG_BYTES (CHUNKV * 16)     // 4096 B per array per stage

__device__ float g_partials[GRID];
__device__ unsigned int g_done_count = 0;   // self-resetting per launch

__device__ __forceinline__ float block_reduce(float x)
{
    __shared__ float swarp[NWARPS];
    #pragma unroll
    for (int off = 16; off > 0; off >>= 1)
        x += __shfl_down_sync(0xFFFFFFFFu, x, off);
    int lane = threadIdx.x & 31;
    int wid  = threadIdx.x >> 5;
    if (lane == 0) swarp[wid] = x;
    __syncthreads();
    if (wid == 0) {
        x = (lane < NWARPS) ? swarp[lane] : 0.0f;
        #pragma unroll
        for (int off = NWARPS / 2; off > 0; off >>= 1)
            x += __shfl_down_sync(0xFFFFFFFFu, x, off);
    }
    return x;  // valid in thread 0
}

__device__ __forceinline__ void mbar_wait_parity(uint32_t mbar, uint32_t parity)
{
    asm volatile(
        "{\n\t"
        ".reg .pred P;\n\t"
        "WAIT_%=:\n\t"
        "mbarrier.try_wait.parity.acquire.cta.shared::cta.b64 P, [%0], %1, 0x989680;\n\t"
        "@!P bra WAIT_%=;\n\t"
        "}"
        :: "r"(mbar), "r"(parity) : "memory");
}

__device__ __forceinline__ void issue_stage(uint32_t mbar, uint32_t dst_p, uint32_t dst_t,
                                            const char* src_p, const char* src_t)
{
    asm volatile("mbarrier.arrive.expect_tx.shared.b64 _, [%0], %1;"
                 :: "r"(mbar), "r"(2u * STG_BYTES) : "memory");
    asm volatile("cp.async.bulk.shared::cta.global.mbarrier::complete_tx::bytes [%0], [%1], %2, [%3];"
                 :: "r"(dst_p), "l"(src_p), "r"((uint32_t)STG_BYTES), "r"(mbar) : "memory");
    asm volatile("cp.async.bulk.shared::cta.global.mbarrier::complete_tx::bytes [%0], [%1], %2, [%3];"
                 :: "r"(dst_t), "l"(src_t), "r"((uint32_t)STG_BYTES), "r"(mbar) : "memory");
}

__device__ __forceinline__ float wabs4(const float4& p, const float4& t, float w)
{
    return fabsf(p.x - t.x) * w + fabsf(p.y - t.y) * (w - 1.0f)
         + fabsf(p.z - t.z) * (w - 2.0f) + fabsf(p.w - t.w) * (w - 3.0f);
}

__global__ __launch_bounds__(BLOCK) void wass_tma_kernel(
    const float* __restrict__ yp, const float* __restrict__ yt,
    float* __restrict__ out)
{
    // 32 KB of staging + 4 mbarriers: in-flight bytes live in SMEM, not regs.
    __shared__ alignas(128) char sbuf[DEPTH][2][STG_BYTES];
    __shared__ alignas(8) uint64_t mbar_storage[DEPTH];

    const int tid = threadIdx.x;
    const int bid = blockIdx.x;

    uint32_t mb[DEPTH];
    #pragma unroll
    for (int d = 0; d < DEPTH; d++)
        mb[d] = (uint32_t)__cvta_generic_to_shared(&mbar_storage[d]);

    if (tid == 0) {
        #pragma unroll
        for (int d = 0; d < DEPTH; d++)
            asm volatile("mbarrier.init.shared.b64 [%0], %1;" :: "r"(mb[d]), "r"(1) : "memory");
        asm volatile("fence.proxy.async.shared::cta;" ::: "memory");
    }
    __syncthreads();

    const char* src_p_base = (const char*)yp + (size_t)bid * VPB * 16;
    const char* src_t_base = (const char*)yt + (size_t)bid * VPB * 16;

    // Prologue: fill the pipeline.
    if (tid == 0) {
        #pragma unroll
        for (int s = 0; s < DEPTH; s++) {
            uint32_t dp = (uint32_t)__cvta_generic_to_shared(&sbuf[s][0][0]);
            uint32_t dt = (uint32_t)__cvta_generic_to_shared(&sbuf[s][1][0]);
            issue_stage(mb[s], dp, dt,
                        src_p_base + (size_t)s * STG_BYTES,
                        src_t_base + (size_t)s * STG_BYTES);
        }
    }

    float acc = 0.0f;

    #pragma unroll
    for (int s = 0; s < NSTG; s++) {
        const int slot = s & (DEPTH - 1);
        const uint32_t parity = (s / DEPTH) & 1;

        mbar_wait_parity(mb[slot], parity);

        const float4* sp = reinterpret_cast<const float4*>(&sbuf[slot][0][0]);
        const float4* st = reinterpret_cast<const float4*>(&sbuf[slot][1][0]);
        float4 p = sp[tid];
        float4 t = st[tid];

        // v = bid*2048 + s*256 + tid; bid*2048 ≡ 0 (mod 1024)
        const int vmod = ((s & 3) * CHUNKV + tid) & (TVEC - 1);
        const float w = (float)(TT - 4 * vmod);
        acc += wabs4(p, t, w);

        __syncthreads();   // all threads done reading this slot

        if (tid == 0 && s + DEPTH < NSTG) {
            const int ns = s + DEPTH;
            uint32_t dp = (uint32_t)__cvta_generic_to_shared(&sbuf[slot][0][0]);
            uint32_t dt = (uint32_t)__cvta_generic_to_shared(&sbuf[slot][1][0]);
            issue_stage(mb[slot], dp, dt,
                        src_p_base + (size_t)ns * STG_BYTES,
                        src_t_base + (size_t)ns * STG_BYTES);
        }
    }

    float bsum = block_reduce(acc);

    __shared__ bool s_is_last;
    if (tid == 0) {
        g_partials[bid] = bsum;
        __threadfence();
        unsigned int n = atomicAdd(&g_done_count, 1u);
        s_is_last = (n == GRID - 1);
        if (s_is_last) g_done_count = 0;       // reset for next graph replay
    }
    __syncthreads();

    if (s_is_last) {
        float a = 0.0f;
        #pragma unroll 4
        for (int i = tid; i < GRID; i += BLOCK)
            a += g_partials[i];
        float total = block_reduce(a);
        if (tid == 0) {
            double scaling = 2.0 / ((double)TT * (double)CC * (double)(TT + 1));
            out[0] = (float)((double)total * scaling / (double)BB);
        }
    }
}

extern "C" void kernel_launch(void* const* d_in, const int* in_sizes, int n_in,
                              void* d_out, int out_size)
{
    const float* yp = reinterpret_cast<const float*>(d_in[0]);
    const float* yt = reinterpret_cast<const float*>(d_in[1]);
    float* out = reinterpret_cast<float*>(d_out);
    wass_tma_kernel<<<GRID, BLOCK>>>(yp, yt, out);
}

// round 12
// speedup vs baseline: 1.2655x; 1.2655x over previous
#include <cuda_runtime.h>
#include <cuda_bf16.h>
#include <cstdint>

// Problem constants
#define BB 32
#define CC 64
#define TT 4096
#define NV8 ((BB * CC * TT) / 8)   // 1,048,576 v8 (32-byte) vectors per array
#define TV8 (TT / 8)                // 512 (power of two)

#define GRID 1024
#define BLOCK 256
#define NWARPS (BLOCK / 32)
#define S (GRID * BLOCK)            // 262,144 v8-stride
#define ITERS (NV8 / S)             // exactly 4

__device__ float g_partials[GRID];
__device__ unsigned int g_done_count = 0;   // self-resetting per launch

__device__ __forceinline__ float block_reduce(float x)
{
    __shared__ float swarp[NWARPS];
    #pragma unroll
    for (int off = 16; off > 0; off >>= 1)
        x += __shfl_down_sync(0xFFFFFFFFu, x, off);
    int lane = threadIdx.x & 31;
    int wid  = threadIdx.x >> 5;
    if (lane == 0) swarp[wid] = x;
    __syncthreads();
    if (wid == 0) {
        x = (lane < NWARPS) ? swarp[lane] : 0.0f;
        #pragma unroll
        for (int off = NWARPS / 2; off > 0; off >>= 1)
            x += __shfl_down_sync(0xFFFFFFFFu, x, off);
    }
    return x;  // valid in thread 0
}

// 256-bit global load (sm_100a): 8 floats in one LDG.
__device__ __forceinline__ void ldg256(const float* a, float r[8])
{
    asm volatile("ld.global.nc.v8.f32 {%0,%1,%2,%3,%4,%5,%6,%7}, [%8];"
                 : "=f"(r[0]), "=f"(r[1]), "=f"(r[2]), "=f"(r[3]),
                   "=f"(r[4]), "=f"(r[5]), "=f"(r[6]), "=f"(r[7])
                 : "l"(a));
}

// R7 envelope (regs<=32, 8 CTAs/SM, occ~84%) with half the LDG instructions:
// 2 x LDG.256 per step = same 64 B/lane in flight as 4 x LDG.128.
__global__ __launch_bounds__(BLOCK, 8) void wass_fused_kernel(
    const float* __restrict__ yp, const float* __restrict__ yt,
    float* __restrict__ out)
{
    const int v0 = blockIdx.x * BLOCK + threadIdx.x;   // v8-vector index

    // S is a multiple of TV8, so (v0 + i*S) mod TV8 is iteration-invariant:
    // one weight base for all 4 iterations.
    const float w = (float)(TT - 8 * (v0 & (TV8 - 1)));

    float acc = 0.0f;

    #pragma unroll
    for (int i = 0; i < ITERS; i++) {
        const float* ap = yp + (size_t)(v0 + i * S) * 8;
        const float* at = yt + (size_t)(v0 + i * S) * 8;

        float p[8], t[8];
        ldg256(ap, p);
        ldg256(at, t);

        float s = 0.0f;
        #pragma unroll
        for (int k = 0; k < 8; k++)
            s += fabsf(p[k] - t[k]) * (w - (float)k);
        acc += s;
    }

    float bsum = block_reduce(acc);

    __shared__ bool s_is_last;
    if (threadIdx.x == 0) {
        g_partials[blockIdx.x] = bsum;
        __threadfence();                       // partial visible before counting
        unsigned int n = atomicAdd(&g_done_count, 1u);
        s_is_last = (n == GRID - 1);
        if (s_is_last) g_done_count = 0;       // reset for next graph replay
    }
    __syncthreads();

    if (s_is_last) {
        // Deterministic final reduce: fixed order over g_partials.
        float a = 0.0f;
        #pragma unroll 4
        for (int i = threadIdx.x; i < GRID; i += BLOCK)
            a += g_partials[i];
        float total = block_reduce(a);
        if (threadIdx.x == 0) {
            double scaling = 2.0 / ((double)TT * (double)CC * (double)(TT + 1));
            out[0] = (float)((double)total * scaling / (double)BB);
        }
    }
}

extern "C" void kernel_launch(void* const* d_in, const int* in_sizes, int n_in,
                              void* d_out, int out_size)
{
    const float* yp = reinterpret_cast<const float*>(d_in[0]);
    const float* yt = reinterpret_cast<const float*>(d_in[1]);
    float* out = reinterpret_cast<float*>(d_out);
    wass_fused_kernel<<<GRID, BLOCK>>>(yp, yt, out);
}

// round 13
// speedup vs baseline: 1.3215x; 1.0442x over previous
#include <cuda_runtime.h>
#include <cuda_bf16.h>
#include <cstdint>

// Problem constants
#define BB 32
#define CC 64
#define TT 4096
#define NVEC ((BB * CC * TT) / 4)   // 2,097,152 float4 vectors
#define TVEC (TT / 4)               // 1024 (power of two)

#define GRID 1024
#define BLOCK 256
#define NWARPS (BLOCK / 32)
#define ITERS (NVEC / (GRID * BLOCK))   // exactly 8

// Fixed-point scale for deterministic integer accumulation.
#define FXP 1048576.0f               // 2^20

__device__ unsigned long long g_total = 0;   // fixed-point grand total
__device__ unsigned int g_done_count = 0;    // self-resetting per launch

__device__ __forceinline__ float block_reduce(float x)
{
    __shared__ float swarp[NWARPS];
    #pragma unroll
    for (int off = 16; off > 0; off >>= 1)
        x += __shfl_down_sync(0xFFFFFFFFu, x, off);
    int lane = threadIdx.x & 31;
    int wid  = threadIdx.x >> 5;
    if (lane == 0) swarp[wid] = x;
    __syncthreads();
    if (wid == 0) {
        x = (lane < NWARPS) ? swarp[lane] : 0.0f;
        #pragma unroll
        for (int off = NWARPS / 2; off > 0; off >>= 1)
            x += __shfl_down_sync(0xFFFFFFFFu, x, off);
    }
    return x;  // valid in thread 0
}

__device__ __forceinline__ float wabs4(const float4& p, const float4& t, float w)
{
    return fabsf(p.x - t.x) * w + fabsf(p.y - t.y) * (w - 1.0f)
         + fabsf(p.z - t.z) * (w - 2.0f) + fabsf(p.w - t.w) * (w - 3.0f);
}

// R7 champion memory loop (regs=32, 8 CTAs/SM, MLP=4) + fixed-point tail:
// integer atomicAdd is order-independent -> deterministic, and the last block's
// epilogue is an 8-byte read instead of 4KB + double block-reduce.
__global__ __launch_bounds__(BLOCK, 8) void wass_fused_kernel(
    const float4* __restrict__ yp, const float4* __restrict__ yt,
    float* __restrict__ out)
{
    const int v0 = blockIdx.x * BLOCK + threadIdx.x;
    const int S  = GRID * BLOCK;

    float acc = 0.0f;

    #pragma unroll
    for (int c = 0; c < ITERS / 2; c++) {
        const int va = v0 + (2 * c + 0) * S;
        const int vb = v0 + (2 * c + 1) * S;

        // 4 loads front-batched before any compute.
        float4 p0 = yp[va];
        float4 t0 = yt[va];
        float4 p1 = yp[vb];
        float4 t1 = yt[vb];

        acc += wabs4(p0, t0, (float)(TT - 4 * (va & (TVEC - 1))));
        acc += wabs4(p1, t1, (float)(TT - 4 * (vb & (TVEC - 1))));
    }

    float bsum = block_reduce(acc);

    __shared__ bool s_is_last;
    if (threadIdx.x == 0) {
        // Deterministic contribution: fixed-point u64, commutative addition.
        unsigned long long q = (unsigned long long)__float2ll_rn((double)bsum * (double)FXP);
        atomicAdd(&g_total, q);
        __threadfence();                       // total visible before counting
        unsigned int n = atomicAdd(&g_done_count, 1u);
        s_is_last = (n == GRID - 1);
        if (s_is_last) {
            // All adds have landed; publish and reset for next graph replay.
            unsigned long long tot = g_total;
            double scaling = 2.0 / ((double)TT * (double)CC * (double)(TT + 1));
            out[0] = (float)(((double)tot / (double)FXP) * scaling / (double)BB);
            g_total = 0ULL;
            g_done_count = 0;
        }
    }
}

extern "C" void kernel_launch(void* const* d_in, const int* in_sizes, int n_in,
                              void* d_out, int out_size)
{
    const float4* yp = reinterpret_cast<const float4*>(d_in[0]);
    const float4* yt = reinterpret_cast<const float4*>(d_in[1]);
    float* out = reinterpret_cast<float*>(d_out);
    wass_fused_kernel<<<GRID, BLOCK>>>(yp, yt, out);
}